// round 12
// baseline (speedup 1.0000x reference)
#include <cuda_runtime.h>
#include <utility>
#include <cstddef>

// ============================================================================
// Compile-time Clifford algebra tables for N_GEN = 6 (DIM = 64).
// ============================================================================

struct Alg {
    int blade[64];
    int cls[64];
    signed char ktab[64][64];   // [j][i] -> k
    signed char sgn[64][64];    // [j][i] -> 1 if negative
    signed char ptab[64][64];   // [j][i] -> w_gp column p
    int P;
};

constexpr int popc6(int x) { int c = 0; for (int b = 0; b < 6; ++b) c += (x >> b) & 1; return c; }

constexpr Alg make_alg() {
    Alg a{};
    int idx = 0;
    for (int g = 0; g <= 6; ++g)
        for (int b = 0; b < 64; ++b)
            if (popc6(b) == g) a.blade[idx++] = b;
    int inv[64] = {};
    for (int i = 0; i < 64; ++i) inv[a.blade[i]] = i;
    for (int i = 0; i < 64; ++i) a.cls[i] = popc6(a.blade[i]) & 3;

    bool paths[64] = {};
    for (int i = 0; i < 64; ++i)
        for (int k = 0; k < 64; ++k) {
            int j = inv[a.blade[i] ^ a.blade[k]];
            paths[a.cls[i] * 16 + a.cls[j] * 4 + a.cls[k]] = true;
        }
    int pmap[64] = {};
    int P = 0;
    for (int t = 0; t < 64; ++t) pmap[t] = paths[t] ? P++ : -1;
    a.P = P;

    for (int j = 0; j < 64; ++j)
        for (int i = 0; i < 64; ++i) {
            int bi = a.blade[i], bj = a.blade[j];
            int bk = bi ^ bj;
            int k = inv[bk];
            a.ktab[j][i] = (signed char)k;
            int s = 0;
            int t = bi >> 1;
            while (t) { s += popc6(t & bk); t >>= 1; }
            a.sgn[j][i] = (signed char)(s & 1);
            a.ptab[j][i] = (signed char)pmap[a.cls[i] * 16 + a.cls[j] * 4 + a.cls[k]];
        }
    return a;
}

constexpr Alg ALG = make_alg();
constexpr int PN = ALG.P;

// ---- Per-row slot plan: group the 64 terms of output row j by w_gp column p.
struct RowPlan {
    signed char slot[64];
    signed char pofs[8];
    signed char first[64];
    int ns;
};

constexpr RowPlan make_plan(int j) {
    RowPlan r{};
    r.ns = 0;
    for (int s = 0; s < 8; ++s) r.pofs[s] = -1;
    for (int i = 0; i < 64; ++i) {
        int p = ALG.ptab[j][i];
        int s = 0;
        for (; s < r.ns; ++s)
            if (r.pofs[s] == p) break;
        r.first[i] = (s == r.ns) ? 1 : 0;
        if (s == r.ns) r.pofs[r.ns++] = (signed char)p;
        r.slot[i] = (signed char)s;
    }
    return r;
}

constexpr bool ns_ok() {
    for (int j = 0; j < 64; ++j)
        if (make_plan(j).ns > 8) return false;
    return true;
}
static_assert(ns_ok(), "row uses more than 8 distinct paths");

// ---- Scalar constexpr wrappers (device sees only folded integers).
template <int J, int I> struct GT {
    static constexpr int  k   = (int)ALG.ktab[J][I];
    static constexpr bool neg = ALG.sgn[J][I] != 0;
    static constexpr int  s   = (int)make_plan(J).slot[I];
    static constexpr bool fst = make_plan(J).first[I] != 0;
};
template <int J, int S> struct SP {
    static constexpr int p = (int)make_plan(J).pofs[S];
};
template <int J> struct RN {
    static constexpr int ns = make_plan(J).ns;
};
template <int I> struct CT {
    static constexpr int c = ALG.cls[I];
};
template <int Q> struct PP {
    static constexpr int cl = ALG.cls[2 * Q];
    static constexpr int ch = ALG.cls[2 * Q + 1];
};

constexpr bool pat_ok() {
    for (int q = 0; q < 32; ++q) {
        int cl = ALG.cls[2 * q], ch = ALG.cls[2 * q + 1];
        bool ok = (cl == 0 && ch == 0) || (cl == 0 && ch == 1) || (cl == 1 && ch == 1) ||
                  (cl == 1 && ch == 2) || (cl == 2 && ch == 2) || (cl == 3 && ch == 3);
        if (!ok) return false;
    }
    return true;
}
static_assert(pat_ok(), "unexpected adjacent class pattern");

static constexpr int NB = 256;   // batch
static constexpr int NF = 128;   // features
static constexpr int DV = 64;    // DIM
static constexpr int XS = 68;    // padded smem row stride (floats), 16B-aligned

// ---------------------------------------------------------------------------
// Packed f32x2 helpers (linear phase)
// ---------------------------------------------------------------------------

using u64 = unsigned long long;

__device__ __forceinline__ u64 fma2(u64 a, u64 b, u64 c) {
    u64 d;
    asm("fma.rn.f32x2 %0, %1, %2, %3;" : "=l"(d) : "l"(a), "l"(b), "l"(c));
    return d;
}

__device__ __forceinline__ u64 pk2(float lo, float hi) {
    u64 r;
    asm("mov.b64 %0, {%1,%2};" : "=l"(r) : "f"(lo), "f"(hi));
    return r;
}

// wp order: [0]=(0,0) [1]=(0,1) [2]=(1,1) [3]=(1,2) [4]=(2,2) [5]=(3,3)
template <int CL, int CH>
__device__ __forceinline__ u64 selw(const u64* wp) {
    if constexpr (CL == 0 && CH == 0) return wp[0];
    else if constexpr (CL == 0 && CH == 1) return wp[1];
    else if constexpr (CL == 1 && CH == 1) return wp[2];
    else if constexpr (CL == 1 && CH == 2) return wp[3];
    else if constexpr (CL == 2 && CH == 2) return wp[4];
    else return wp[5];  // (3,3)
}

template <std::size_t... Ts>
__device__ __forceinline__ void lin_m2(u64* acc2, const u64* wp, const ulonglong2* xm,
                                       std::index_sequence<Ts...>) {
    ([&] {
        const ulonglong2 v = xm[Ts];
        acc2[2 * Ts]     = fma2(v.x, selw<PP<2 * (int)Ts>::cl,     PP<2 * (int)Ts>::ch>(wp),
                                acc2[2 * Ts]);
        acc2[2 * Ts + 1] = fma2(v.y, selw<PP<2 * (int)Ts + 1>::cl, PP<2 * (int)Ts + 1>::ch>(wp),
                                acc2[2 * Ts + 1]);
    }(), ...);
}

// ---------------------------------------------------------------------------
// Misc template helpers
// ---------------------------------------------------------------------------

template <std::size_t... Is>
__device__ __forceinline__ void sq_accum(float* sq, const float* acc, std::index_sequence<Is...>) {
    ((sq[CT<(int)Is>::c] = fmaf(acc[Is], acc[Is], sq[CT<(int)Is>::c])), ...);
}

template <std::size_t... Is>
__device__ __forceinline__ void xr_scale(float* xr, const float* acc, const float* inv,
                                         std::index_sequence<Is...>) {
    ((xr[Is] = acc[Is] * inv[CT<(int)Is>::c]), ...);
}

// ---------------------------------------------------------------------------
// GP phase: sign-folded slot accumulation (1 FFMA per term).
// ---------------------------------------------------------------------------

template <int J, int I>
__device__ __forceinline__ void gp_term(float* S, const float* xv, const float* xr) {
    const float xrk = GT<J, I>::neg ? -xr[GT<J, I>::k] : xr[GT<J, I>::k];
    if constexpr (GT<J, I>::fst)
        S[GT<J, I>::s] = xv[I] * xrk;
    else
        S[GT<J, I>::s] = fmaf(xv[I], xrk, S[GT<J, I>::s]);
}

template <int J, int S8>
__device__ __forceinline__ void gp_comb(float& acc, const float* S, const float* w) {
    if constexpr (S8 < RN<J>::ns) acc = fmaf(w[SP<J, S8>::p], S[S8], acc);
}

template <int J, std::size_t... Is>
__device__ __forceinline__ float gp_row(const float* xv, const float* xr, const float* w,
                                        std::index_sequence<Is...>) {
    float S[8];
    (gp_term<J, (int)Is>(S, xv, xr), ...);
    float acc = 0.f;
    gp_comb<J, 0>(acc, S, w); gp_comb<J, 1>(acc, S, w);
    gp_comb<J, 2>(acc, S, w); gp_comb<J, 3>(acc, S, w);
    gp_comb<J, 4>(acc, S, w); gp_comb<J, 5>(acc, S, w);
    gp_comb<J, 6>(acc, S, w); gp_comb<J, 7>(acc, S, w);
    return acc;
}

template <int G>
__device__ __forceinline__ void gp_group(float* __restrict__ orow, const float* xv,
                                         const float* xr, const float* w) {
    float4 v;
    v.x = gp_row<4 * G + 0>(xv, xr, w, std::make_index_sequence<64>{});
    v.y = gp_row<4 * G + 1>(xv, xr, w, std::make_index_sequence<64>{});
    v.z = gp_row<4 * G + 2>(xv, xr, w, std::make_index_sequence<64>{});
    v.w = gp_row<4 * G + 3>(xv, xr, w, std::make_index_sequence<64>{});
    *reinterpret_cast<float4*>(orow + 4 * G) = v;
}

template <std::size_t... Gs>
__device__ __forceinline__ void gp_all(float* __restrict__ orow, const float* xv, const float* xr,
                                       const float* w, std::index_sequence<Gs...>) {
    (gp_group<(int)Gs>(orow, xv, xr, w), ...);
}

// ---------------------------------------------------------------------------
// Pre-packed weights, SoA: three [m][n] arrays of ulonglong2, each holding
// two ready-to-use f32x2 multiplier pairs:
//   g_wp0[m][n] = { (x,x), (x,y) }   -> wp[0], wp[1]
//   g_wp1[m][n] = { (y,y), (y,z) }   -> wp[2], wp[3]
//   g_wp2[m][n] = { (z,z), (w,w) }   -> wp[4], wp[5]
// Built by a tiled transpose (both gmem sides coalesced).
// ---------------------------------------------------------------------------

__device__ ulonglong2 g_wp0[NF * NF];
__device__ ulonglong2 g_wp1[NF * NF];
__device__ ulonglong2 g_wp2[NF * NF];

__global__ void wlp_kernel(const float4* __restrict__ w) {
    __shared__ float4 t[16][17];
    const int mb = blockIdx.x & 7;
    const int nb = blockIdx.x >> 3;
    const int tm = threadIdx.x & 15;
    const int tn = threadIdx.x >> 4;

    // Read w_lin[n][m] coalesced in m.
    t[tn][tm] = w[(nb * 16 + tn) * NF + (mb * 16 + tm)];
    __syncthreads();

    const float4 v = t[tm][tn];            // = w_lin[nb*16+tm][mb*16+tn]
    const int m = mb * 16 + tn;
    const int n = nb * 16 + tm;
    const int o = m * NF + n;              // writes coalesced in n (tm fastest)

    ulonglong2 A, B, C;
    A.x = pk2(v.x, v.x); A.y = pk2(v.x, v.y);
    B.x = pk2(v.y, v.y); B.y = pk2(v.y, v.z);
    C.x = pk2(v.z, v.z); C.y = pk2(v.w, v.w);
    g_wp0[o] = A;
    g_wp1[o] = B;
    g_wp2[o] = C;
}

// ---------------------------------------------------------------------------
// Fused kernel: one CTA per batch element b, one thread per feature n.
// ---------------------------------------------------------------------------

__global__ void __launch_bounds__(128, 2)
qgp_kernel(const float* __restrict__ x, const float* __restrict__ w_gp,
           const float* __restrict__ b_lin, const float* __restrict__ a_norm,
           float* __restrict__ out) {
    __shared__ __align__(16) float x_s[NF * XS];   // x tile; reused for output staging

    const int b = blockIdx.x;
    const int n = threadIdx.x;

    // Hoisted scalar loads (latency hidden under the m-loop).
    const float bl  = b_lin[n];
    const float4 an4 = *reinterpret_cast<const float4*>(a_norm + n * 4);

    // Stage x[b] into smem (coalesced gmem reads, padded smem rows).
    {
        const float4* xg = reinterpret_cast<const float4*>(x + (size_t)b * NF * DV);
#pragma unroll
        for (int t = 0; t < 16; ++t) {
            int idx = t * 128 + n;
            int m = idx >> 4, c = idx & 15;
            *reinterpret_cast<float4*>(x_s + m * XS + c * 4) = xg[idx];
        }
    }
    __syncthreads();

    // ---- Linear phase (packed f32x2): xr[n,i] = sum_m x[b,m,i] * w_lin[n,m,cls[i]] ----
    u64 acc2[32];
#pragma unroll
    for (int q = 0; q < 32; ++q) acc2[q] = 0ull;

    const ulonglong2* p0 = g_wp0 + n;
    const ulonglong2* p1 = g_wp1 + n;
    const ulonglong2* p2 = g_wp2 + n;

#pragma unroll 4
    for (int m = 0; m < NF; ++m) {
        const ulonglong2 a = p0[m * NF];   // 3 independent coalesced LDG.128 streams
        const ulonglong2 bb = p1[m * NF];
        const ulonglong2 c = p2[m * NF];
        u64 wp[6];
        wp[0] = a.x;  wp[1] = a.y;
        wp[2] = bb.x; wp[3] = bb.y;
        wp[4] = c.x;  wp[5] = c.y;
        const ulonglong2* xm = reinterpret_cast<const ulonglong2*>(x_s + m * XS);
        lin_m2(acc2, wp, xm, std::make_index_sequence<16>{});
    }

    float acc[DV];
#pragma unroll
    for (int q = 0; q < 32; ++q)
        asm("mov.b64 {%0,%1}, %2;" : "=f"(acc[2 * q]), "=f"(acc[2 * q + 1]) : "l"(acc2[q]));

    acc[0] += bl;

    // ---- Norms per class, sigmoid gate, scale ----
    float sq[4] = {0.f, 0.f, 0.f, 0.f};
    sq_accum(sq, acc, std::make_index_sequence<64>{});

    float inv[4];
    {
        const float anv[4] = {an4.x, an4.y, an4.z, an4.w};
#pragma unroll
        for (int c = 0; c < 4; ++c) {
            float nrm = sqrtf(sq[c]);
            float sig = 1.f / (1.f + expf(-anv[c]));
            float gate = fmaf(sig, nrm - 1.f, 1.f);
            inv[c] = 1.f / (gate + 1e-6f);
        }
    }

    float xr[DV];
    xr_scale(xr, acc, inv, std::make_index_sequence<64>{});

    // ---- xv = x[b,n,:] straight from smem (row m == n) ----
    float xv[DV];
#pragma unroll
    for (int t = 0; t < 16; ++t) {
        float4 v = *reinterpret_cast<const float4*>(x_s + n * XS + 4 * t);
        xv[4 * t + 0] = v.x;
        xv[4 * t + 1] = v.y;
        xv[4 * t + 2] = v.z;
        xv[4 * t + 3] = v.w;
    }

    // ---- w_gp row (16 KB total, L2-resident across CTAs) ----
    float w[PN];
    {
        const float4* wg = reinterpret_cast<const float4*>(w_gp + (size_t)n * PN);
#pragma unroll
        for (int t = 0; t < PN / 4; ++t) {
            float4 v = wg[t];
            w[4 * t + 0] = v.x;
            w[4 * t + 1] = v.y;
            w[4 * t + 2] = v.z;
            w[4 * t + 3] = v.w;
        }
    }

    __syncthreads();   // everyone done reading x_s; reuse it for output staging

    // ---- Geometric product into smem row, then coalesced copy to gmem ----
    gp_all(x_s + n * XS, xv, xr, w, std::make_index_sequence<16>{});
    __syncthreads();

    {
        float4* og = reinterpret_cast<float4*>(out + (size_t)b * NF * DV);
#pragma unroll
        for (int t = 0; t < 16; ++t) {
            int idx = t * 128 + n;
            int m = idx >> 4, c = idx & 15;
            og[idx] = *reinterpret_cast<const float4*>(x_s + m * XS + c * 4);
        }
    }
}

// ---------------------------------------------------------------------------

extern "C" void kernel_launch(void* const* d_in, const int* in_sizes, int n_in,
                              void* d_out, int out_size) {
    (void)in_sizes; (void)n_in; (void)out_size;
    const float* x      = (const float*)d_in[0];
    const float* w_gp   = (const float*)d_in[1];
    const float* w_lin  = (const float*)d_in[2];
    const float* b_lin  = (const float*)d_in[3];
    const float* a_norm = (const float*)d_in[4];
    float* out = (float*)d_out;

    wlp_kernel<<<64, 256>>>((const float4*)w_lin);
    qgp_kernel<<<NB, NF>>>(x, w_gp, b_lin, a_norm, out);
}

// round 13
// speedup vs baseline: 1.7181x; 1.7181x over previous
#include <cuda_runtime.h>
#include <utility>
#include <cstddef>

// ============================================================================
// Compile-time Clifford algebra tables for N_GEN = 6 (DIM = 64).
// ============================================================================

struct Alg {
    int blade[64];
    int cls[64];
    signed char ktab[64][64];   // [j][i] -> k
    signed char sgn[64][64];    // [j][i] -> 1 if negative
    signed char ptab[64][64];   // [j][i] -> w_gp column p
    int P;
};

constexpr int popc6(int x) { int c = 0; for (int b = 0; b < 6; ++b) c += (x >> b) & 1; return c; }

constexpr Alg make_alg() {
    Alg a{};
    int idx = 0;
    for (int g = 0; g <= 6; ++g)
        for (int b = 0; b < 64; ++b)
            if (popc6(b) == g) a.blade[idx++] = b;
    int inv[64] = {};
    for (int i = 0; i < 64; ++i) inv[a.blade[i]] = i;
    for (int i = 0; i < 64; ++i) a.cls[i] = popc6(a.blade[i]) & 3;

    bool paths[64] = {};
    for (int i = 0; i < 64; ++i)
        for (int k = 0; k < 64; ++k) {
            int j = inv[a.blade[i] ^ a.blade[k]];
            paths[a.cls[i] * 16 + a.cls[j] * 4 + a.cls[k]] = true;
        }
    int pmap[64] = {};
    int P = 0;
    for (int t = 0; t < 64; ++t) pmap[t] = paths[t] ? P++ : -1;
    a.P = P;

    for (int j = 0; j < 64; ++j)
        for (int i = 0; i < 64; ++i) {
            int bi = a.blade[i], bj = a.blade[j];
            int bk = bi ^ bj;
            int k = inv[bk];
            a.ktab[j][i] = (signed char)k;
            int s = 0;
            int t = bi >> 1;
            while (t) { s += popc6(t & bk); t >>= 1; }
            a.sgn[j][i] = (signed char)(s & 1);
            a.ptab[j][i] = (signed char)pmap[a.cls[i] * 16 + a.cls[j] * 4 + a.cls[k]];
        }
    return a;
}

constexpr Alg ALG = make_alg();
constexpr int PN = ALG.P;

// ---- Per-row slot plan: group the 64 terms of output row j by w_gp column p.
struct RowPlan {
    signed char slot[64];
    signed char pofs[8];
    signed char first[64];
    int ns;
};

constexpr RowPlan make_plan(int j) {
    RowPlan r{};
    r.ns = 0;
    for (int s = 0; s < 8; ++s) r.pofs[s] = -1;
    for (int i = 0; i < 64; ++i) {
        int p = ALG.ptab[j][i];
        int s = 0;
        for (; s < r.ns; ++s)
            if (r.pofs[s] == p) break;
        r.first[i] = (s == r.ns) ? 1 : 0;
        if (s == r.ns) r.pofs[r.ns++] = (signed char)p;
        r.slot[i] = (signed char)s;
    }
    return r;
}

constexpr bool ns_ok() {
    for (int j = 0; j < 64; ++j)
        if (make_plan(j).ns > 8) return false;
    return true;
}
static_assert(ns_ok(), "row uses more than 8 distinct paths");

// ---- Scalar constexpr wrappers (device sees only folded integers).
template <int J, int I> struct GT {
    static constexpr int  k   = (int)ALG.ktab[J][I];
    static constexpr bool neg = ALG.sgn[J][I] != 0;
    static constexpr int  s   = (int)make_plan(J).slot[I];
    static constexpr bool fst = make_plan(J).first[I] != 0;
};
template <int J, int S> struct SP {
    static constexpr int p = (int)make_plan(J).pofs[S];
};
template <int J> struct RN {
    static constexpr int ns = make_plan(J).ns;
};
template <int I> struct CT {
    static constexpr int c = ALG.cls[I];
};
template <int Q> struct PP {
    static constexpr int cl = ALG.cls[2 * Q];
    static constexpr int ch = ALG.cls[2 * Q + 1];
};

constexpr bool pat_ok() {
    for (int q = 0; q < 32; ++q) {
        int cl = ALG.cls[2 * q], ch = ALG.cls[2 * q + 1];
        bool ok = (cl == 0 && ch == 0) || (cl == 0 && ch == 1) || (cl == 1 && ch == 1) ||
                  (cl == 1 && ch == 2) || (cl == 2 && ch == 2) || (cl == 3 && ch == 3);
        if (!ok) return false;
    }
    return true;
}
static_assert(pat_ok(), "unexpected adjacent class pattern");

static constexpr int NB = 256;   // batch
static constexpr int NF = 128;   // features
static constexpr int DV = 64;    // DIM
static constexpr int XS = 68;    // padded smem row stride (floats), 16B-aligned

// ---------------------------------------------------------------------------
// Packed f32x2 helpers (linear phase)
// ---------------------------------------------------------------------------

using u64 = unsigned long long;

__device__ __forceinline__ u64 fma2(u64 a, u64 b, u64 c) {
    u64 d;
    asm("fma.rn.f32x2 %0, %1, %2, %3;" : "=l"(d) : "l"(a), "l"(b), "l"(c));
    return d;
}

// wp order: [0]=(0,0) [1]=(0,1) [2]=(1,1) [3]=(1,2) [4]=(2,2) [5]=(3,3)
template <int CL, int CH>
__device__ __forceinline__ u64 selw(const u64* wp) {
    if constexpr (CL == 0 && CH == 0) return wp[0];
    else if constexpr (CL == 0 && CH == 1) return wp[1];
    else if constexpr (CL == 1 && CH == 1) return wp[2];
    else if constexpr (CL == 1 && CH == 2) return wp[3];
    else if constexpr (CL == 2 && CH == 2) return wp[4];
    else return wp[5];  // (3,3)
}

template <std::size_t... Ts>
__device__ __forceinline__ void lin_m2(u64* acc2, const u64* wp, const ulonglong2* xm,
                                       std::index_sequence<Ts...>) {
    ([&] {
        const ulonglong2 v = xm[Ts];
        acc2[2 * Ts]     = fma2(v.x, selw<PP<2 * (int)Ts>::cl,     PP<2 * (int)Ts>::ch>(wp),
                                acc2[2 * Ts]);
        acc2[2 * Ts + 1] = fma2(v.y, selw<PP<2 * (int)Ts + 1>::cl, PP<2 * (int)Ts + 1>::ch>(wp),
                                acc2[2 * Ts + 1]);
    }(), ...);
}

// ---------------------------------------------------------------------------
// Misc template helpers
// ---------------------------------------------------------------------------

template <std::size_t... Is>
__device__ __forceinline__ void sq_accum(float* sq, const float* acc, std::index_sequence<Is...>) {
    ((sq[CT<(int)Is>::c] = fmaf(acc[Is], acc[Is], sq[CT<(int)Is>::c])), ...);
}

template <std::size_t... Is>
__device__ __forceinline__ void xr_scale(float* xr, const float* acc, const float* inv,
                                         std::index_sequence<Is...>) {
    ((xr[Is] = acc[Is] * inv[CT<(int)Is>::c]), ...);
}

// ---------------------------------------------------------------------------
// GP phase: sign-folded slot accumulation (1 FFMA per term).
// ---------------------------------------------------------------------------

template <int J, int I>
__device__ __forceinline__ void gp_term(float* S, const float* xv, const float* xr) {
    const float xrk = GT<J, I>::neg ? -xr[GT<J, I>::k] : xr[GT<J, I>::k];
    if constexpr (GT<J, I>::fst)
        S[GT<J, I>::s] = xv[I] * xrk;
    else
        S[GT<J, I>::s] = fmaf(xv[I], xrk, S[GT<J, I>::s]);
}

template <int J, int S8>
__device__ __forceinline__ void gp_comb(float& acc, const float* S, const float* w) {
    if constexpr (S8 < RN<J>::ns) acc = fmaf(w[SP<J, S8>::p], S[S8], acc);
}

template <int J, std::size_t... Is>
__device__ __forceinline__ float gp_row(const float* xv, const float* xr, const float* w,
                                        std::index_sequence<Is...>) {
    float S[8];
    (gp_term<J, (int)Is>(S, xv, xr), ...);
    float acc = 0.f;
    gp_comb<J, 0>(acc, S, w); gp_comb<J, 1>(acc, S, w);
    gp_comb<J, 2>(acc, S, w); gp_comb<J, 3>(acc, S, w);
    gp_comb<J, 4>(acc, S, w); gp_comb<J, 5>(acc, S, w);
    gp_comb<J, 6>(acc, S, w); gp_comb<J, 7>(acc, S, w);
    return acc;
}

template <int G>
__device__ __forceinline__ void gp_group(float* __restrict__ orow, const float* xv,
                                         const float* xr, const float* w) {
    float4 v;
    v.x = gp_row<4 * G + 0>(xv, xr, w, std::make_index_sequence<64>{});
    v.y = gp_row<4 * G + 1>(xv, xr, w, std::make_index_sequence<64>{});
    v.z = gp_row<4 * G + 2>(xv, xr, w, std::make_index_sequence<64>{});
    v.w = gp_row<4 * G + 3>(xv, xr, w, std::make_index_sequence<64>{});
    *reinterpret_cast<float4*>(orow + 4 * G) = v;
}

template <std::size_t... Gs>
__device__ __forceinline__ void gp_all(float* __restrict__ orow, const float* xv, const float* xr,
                                       const float* w, std::index_sequence<Gs...>) {
    (gp_group<(int)Gs>(orow, xv, xr, w), ...);
}

// ---------------------------------------------------------------------------
// Transposed w_lin scratch: [m][n] float4, tiled transpose (both sides coalesced).
// ---------------------------------------------------------------------------

__device__ float4 g_wlt[NF * NF];

__global__ void wlt_kernel(const float4* __restrict__ w) {
    __shared__ float4 t[16][17];
    const int mb = blockIdx.x & 7;
    const int nb = blockIdx.x >> 3;
    const int tm = threadIdx.x & 15;
    const int tn = threadIdx.x >> 4;

    t[tn][tm] = w[(nb * 16 + tn) * NF + (mb * 16 + tm)];
    __syncthreads();
    g_wlt[(mb * 16 + tn) * NF + (nb * 16 + tm)] = t[tm][tn];
}

// ---------------------------------------------------------------------------
// Fused kernel: one CTA per batch element b, one thread per feature n.
// ---------------------------------------------------------------------------

__global__ void __launch_bounds__(128, 2)
qgp_kernel(const float* __restrict__ x, const float* __restrict__ w_gp,
           const float* __restrict__ b_lin, const float* __restrict__ a_norm,
           float* __restrict__ out) {
    __shared__ __align__(16) float x_s[NF * XS];   // x tile; reused for output staging

    const int b = blockIdx.x;
    const int n = threadIdx.x;

    // Hoisted small loads — latency hidden under the m-loop.
    const float bl   = b_lin[n];
    const float4 an4 = *reinterpret_cast<const float4*>(a_norm + n * 4);

    // w_gp row hoisted above the m-loop: its L2 latency hides under ~6k instrs.
    float w[PN];
    {
        const float4* wg = reinterpret_cast<const float4*>(w_gp + (size_t)n * PN);
#pragma unroll
        for (int t = 0; t < PN / 4; ++t) {
            float4 v = wg[t];
            w[4 * t + 0] = v.x;
            w[4 * t + 1] = v.y;
            w[4 * t + 2] = v.z;
            w[4 * t + 3] = v.w;
        }
    }

    // Stage x[b] into smem (coalesced gmem reads, padded smem rows).
    {
        const float4* xg = reinterpret_cast<const float4*>(x + (size_t)b * NF * DV);
#pragma unroll
        for (int t = 0; t < 16; ++t) {
            int idx = t * 128 + n;
            int m = idx >> 4, c = idx & 15;
            *reinterpret_cast<float4*>(x_s + m * XS + c * 4) = xg[idx];
        }
    }
    __syncthreads();

    // ---- Linear phase (packed f32x2): xr[n,i] = sum_m x[b,m,i] * w_lin[n,m,cls[i]] ----
    u64 acc2[32];
#pragma unroll
    for (int q = 0; q < 32; ++q) acc2[q] = 0ull;

#pragma unroll 8
    for (int m = 0; m < NF; ++m) {
        const float4 w4 = g_wlt[m * NF + n];   // coalesced across lanes, L2-resident
        u64 wp[6];
        asm("mov.b64 %0, {%1,%1};" : "=l"(wp[0]) : "f"(w4.x));
        asm("mov.b64 %0, {%1,%2};" : "=l"(wp[1]) : "f"(w4.x), "f"(w4.y));
        asm("mov.b64 %0, {%1,%1};" : "=l"(wp[2]) : "f"(w4.y));
        asm("mov.b64 %0, {%1,%2};" : "=l"(wp[3]) : "f"(w4.y), "f"(w4.z));
        asm("mov.b64 %0, {%1,%1};" : "=l"(wp[4]) : "f"(w4.z));
        asm("mov.b64 %0, {%1,%1};" : "=l"(wp[5]) : "f"(w4.w));
        const ulonglong2* xm = reinterpret_cast<const ulonglong2*>(x_s + m * XS);
        lin_m2(acc2, wp, xm, std::make_index_sequence<16>{});
    }

    float acc[DV];
#pragma unroll
    for (int q = 0; q < 32; ++q)
        asm("mov.b64 {%0,%1}, %2;" : "=f"(acc[2 * q]), "=f"(acc[2 * q + 1]) : "l"(acc2[q]));

    acc[0] += bl;

    // ---- Norms per class, sigmoid gate, scale ----
    float sq[4] = {0.f, 0.f, 0.f, 0.f};
    sq_accum(sq, acc, std::make_index_sequence<64>{});

    float inv[4];
    {
        const float anv[4] = {an4.x, an4.y, an4.z, an4.w};
#pragma unroll
        for (int c = 0; c < 4; ++c) {
            float nrm = sqrtf(sq[c]);
            float sig = 1.f / (1.f + expf(-anv[c]));
            float gate = fmaf(sig, nrm - 1.f, 1.f);
            inv[c] = 1.f / (gate + 1e-6f);
        }
    }

    float xr[DV];
    xr_scale(xr, acc, inv, std::make_index_sequence<64>{});

    // ---- xv = x[b,n,:] straight from smem (row m == n) ----
    float xv[DV];
#pragma unroll
    for (int t = 0; t < 16; ++t) {
        float4 v = *reinterpret_cast<const float4*>(x_s + n * XS + 4 * t);
        xv[4 * t + 0] = v.x;
        xv[4 * t + 1] = v.y;
        xv[4 * t + 2] = v.z;
        xv[4 * t + 3] = v.w;
    }

    __syncthreads();   // everyone done reading x_s; reuse it for output staging

    // ---- Geometric product into smem row, then coalesced copy to gmem ----
    gp_all(x_s + n * XS, xv, xr, w, std::make_index_sequence<16>{});
    __syncthreads();

    {
        float4* og = reinterpret_cast<float4*>(out + (size_t)b * NF * DV);
#pragma unroll
        for (int t = 0; t < 16; ++t) {
            int idx = t * 128 + n;
            int m = idx >> 4, c = idx & 15;
            og[idx] = *reinterpret_cast<const float4*>(x_s + m * XS + c * 4);
        }
    }
}

// ---------------------------------------------------------------------------

extern "C" void kernel_launch(void* const* d_in, const int* in_sizes, int n_in,
                              void* d_out, int out_size) {
    (void)in_sizes; (void)n_in; (void)out_size;
    const float* x      = (const float*)d_in[0];
    const float* w_gp   = (const float*)d_in[1];
    const float* w_lin  = (const float*)d_in[2];
    const float* b_lin  = (const float*)d_in[3];
    const float* a_norm = (const float*)d_in[4];
    float* out = (float*)d_out;

    wlt_kernel<<<64, 256>>>((const float4*)w_lin);
    qgp_kernel<<<NB, NF>>>(x, w_gp, b_lin, a_norm, out);
}

// round 14
// speedup vs baseline: 1.8178x; 1.0580x over previous
#include <cuda_runtime.h>
#include <utility>
#include <cstddef>

// ============================================================================
// Compile-time Clifford algebra tables for N_GEN = 6 (DIM = 64).
// ============================================================================

struct Alg {
    int blade[64];
    int cls[64];
    signed char ktab[64][64];   // [j][i] -> k   (canonical indices)
    signed char sgn[64][64];    // [j][i] -> 1 if negative
    signed char ptab[64][64];   // [j][i] -> w_gp column p
    int P;
};

constexpr int popc6(int x) { int c = 0; for (int b = 0; b < 6; ++b) c += (x >> b) & 1; return c; }

constexpr Alg make_alg() {
    Alg a{};
    int idx = 0;
    for (int g = 0; g <= 6; ++g)
        for (int b = 0; b < 64; ++b)
            if (popc6(b) == g) a.blade[idx++] = b;
    int inv[64] = {};
    for (int i = 0; i < 64; ++i) inv[a.blade[i]] = i;
    for (int i = 0; i < 64; ++i) a.cls[i] = popc6(a.blade[i]) & 3;

    bool paths[64] = {};
    for (int i = 0; i < 64; ++i)
        for (int k = 0; k < 64; ++k) {
            int j = inv[a.blade[i] ^ a.blade[k]];
            paths[a.cls[i] * 16 + a.cls[j] * 4 + a.cls[k]] = true;
        }
    int pmap[64] = {};
    int P = 0;
    for (int t = 0; t < 64; ++t) pmap[t] = paths[t] ? P++ : -1;
    a.P = P;

    for (int j = 0; j < 64; ++j)
        for (int i = 0; i < 64; ++i) {
            int bi = a.blade[i], bj = a.blade[j];
            int bk = bi ^ bj;
            int k = inv[bk];
            a.ktab[j][i] = (signed char)k;
            int s = 0;
            int t = bi >> 1;
            while (t) { s += popc6(t & bk); t >>= 1; }
            a.sgn[j][i] = (signed char)(s & 1);
            a.ptab[j][i] = (signed char)pmap[a.cls[i] * 16 + a.cls[j] * 4 + a.cls[k]];
        }
    return a;
}

constexpr Alg ALG = make_alg();
constexpr int PN = ALG.P;

// ============================================================================
// Class-blocked permutation of the i-axis.
//   perm[q]  = canonical index stored at internal position q
//   iperm[i] = internal position of canonical index i
// Indices grouped by cls (sizes 16,12,16,20 — each 4-divisible), so every
// aligned quad of internal positions has a single class.
// ============================================================================

struct Perm { int perm[64]; int iperm[64]; };

constexpr Perm make_perm() {
    Perm p{};
    int pos = 0;
    for (int c = 0; c < 4; ++c)
        for (int i = 0; i < 64; ++i)
            if (ALG.cls[i] == c) { p.perm[pos] = i; p.iperm[i] = pos; ++pos; }
    return p;
}

constexpr Perm PR = make_perm();

constexpr bool perm_ok() {
    for (int i = 0; i < 64; ++i)
        if (PR.perm[PR.iperm[i]] != i) return false;
    for (int t = 0; t < 16; ++t) {
        int c = ALG.cls[PR.perm[4 * t]];
        for (int r = 1; r < 4; ++r)
            if (ALG.cls[PR.perm[4 * t + r]] != c) return false;
    }
    return PR.iperm[0] == 0;   // bias target is internal position 0
}
static_assert(perm_ok(), "permutation invalid");

// ---- Per-row slot plan over INTERNAL iteration order q = 0..63.
struct RowPlan {
    signed char slot[64];
    signed char pofs[8];
    signed char first[64];
    int ns;
};

constexpr RowPlan make_plan(int j) {
    RowPlan r{};
    r.ns = 0;
    for (int s = 0; s < 8; ++s) r.pofs[s] = -1;
    for (int q = 0; q < 64; ++q) {
        int p = ALG.ptab[j][PR.perm[q]];
        int s = 0;
        for (; s < r.ns; ++s)
            if (r.pofs[s] == p) break;
        r.first[q] = (s == r.ns) ? 1 : 0;
        if (s == r.ns) r.pofs[r.ns++] = (signed char)p;
        r.slot[q] = (signed char)s;
    }
    return r;
}

constexpr bool ns_ok() {
    for (int j = 0; j < 64; ++j)
        if (make_plan(j).ns > 8) return false;
    return true;
}
static_assert(ns_ok(), "row uses more than 8 distinct paths");

// ---- Scalar constexpr wrappers (device sees only folded integers).
//      Q/I parameters are INTERNAL positions; J is canonical output row.
template <int J, int Q> struct GT {
    static constexpr int  ci  = PR.perm[Q];                       // canonical i
    static constexpr int  k   = PR.iperm[(int)ALG.ktab[J][ci]];   // internal k
    static constexpr bool neg = ALG.sgn[J][ci] != 0;
    static constexpr int  s   = (int)make_plan(J).slot[Q];
    static constexpr bool fst = make_plan(J).first[Q] != 0;
};
template <int J, int S> struct SP {
    static constexpr int p = (int)make_plan(J).pofs[S];
};
template <int J> struct RN {
    static constexpr int ns = make_plan(J).ns;
};
template <int Q> struct CLI {                                      // internal cls
    static constexpr int c = ALG.cls[PR.perm[Q]];
};
template <int T> struct QC {                                       // quad class
    static constexpr int c = ALG.cls[PR.perm[4 * T]];
};

static constexpr int NB = 256;   // batch
static constexpr int NF = 128;   // features
static constexpr int DV = 64;    // DIM
static constexpr int XS = 68;    // padded smem row stride (floats), 16B-aligned

// Internal-position table for the x staging scatter (runtime lookup).
__constant__ int c_iperm[64] = {
    PR.iperm[0],  PR.iperm[1],  PR.iperm[2],  PR.iperm[3],
    PR.iperm[4],  PR.iperm[5],  PR.iperm[6],  PR.iperm[7],
    PR.iperm[8],  PR.iperm[9],  PR.iperm[10], PR.iperm[11],
    PR.iperm[12], PR.iperm[13], PR.iperm[14], PR.iperm[15],
    PR.iperm[16], PR.iperm[17], PR.iperm[18], PR.iperm[19],
    PR.iperm[20], PR.iperm[21], PR.iperm[22], PR.iperm[23],
    PR.iperm[24], PR.iperm[25], PR.iperm[26], PR.iperm[27],
    PR.iperm[28], PR.iperm[29], PR.iperm[30], PR.iperm[31],
    PR.iperm[32], PR.iperm[33], PR.iperm[34], PR.iperm[35],
    PR.iperm[36], PR.iperm[37], PR.iperm[38], PR.iperm[39],
    PR.iperm[40], PR.iperm[41], PR.iperm[42], PR.iperm[43],
    PR.iperm[44], PR.iperm[45], PR.iperm[46], PR.iperm[47],
    PR.iperm[48], PR.iperm[49], PR.iperm[50], PR.iperm[51],
    PR.iperm[52], PR.iperm[53], PR.iperm[54], PR.iperm[55],
    PR.iperm[56], PR.iperm[57], PR.iperm[58], PR.iperm[59],
    PR.iperm[60], PR.iperm[61], PR.iperm[62], PR.iperm[63]
};

// ---------------------------------------------------------------------------
// Packed f32x2 helpers (linear phase)
// ---------------------------------------------------------------------------

using u64 = unsigned long long;

__device__ __forceinline__ u64 fma2(u64 a, u64 b, u64 c) {
    u64 d;
    asm("fma.rn.f32x2 %0, %1, %2, %3;" : "=l"(d) : "l"(a), "l"(b), "l"(c));
    return d;
}

// Single-class quads: one broadcast multiplier per quad.
template <std::size_t... Ts>
__device__ __forceinline__ void lin_m2(u64* acc2, const u64* wq, const ulonglong2* xm,
                                       std::index_sequence<Ts...>) {
    ([&] {
        const ulonglong2 v = xm[Ts];
        acc2[2 * Ts]     = fma2(v.x, wq[QC<(int)Ts>::c], acc2[2 * Ts]);
        acc2[2 * Ts + 1] = fma2(v.y, wq[QC<(int)Ts>::c], acc2[2 * Ts + 1]);
    }(), ...);
}

// ---------------------------------------------------------------------------
// Misc template helpers (internal index space)
// ---------------------------------------------------------------------------

template <std::size_t... Qs>
__device__ __forceinline__ void sq_accum(float* sq, const float* acc, std::index_sequence<Qs...>) {
    ((sq[CLI<(int)Qs>::c] = fmaf(acc[Qs], acc[Qs], sq[CLI<(int)Qs>::c])), ...);
}

template <std::size_t... Qs>
__device__ __forceinline__ void xr_scale(float* xr, const float* acc, const float* inv,
                                         std::index_sequence<Qs...>) {
    ((xr[Qs] = acc[Qs] * inv[CLI<(int)Qs>::c]), ...);
}

// ---------------------------------------------------------------------------
// GP phase: sign-folded slot accumulation (1 FFMA per term), internal order.
// ---------------------------------------------------------------------------

template <int J, int Q>
__device__ __forceinline__ void gp_term(float* S, const float* xv, const float* xr) {
    const float xrk = GT<J, Q>::neg ? -xr[GT<J, Q>::k] : xr[GT<J, Q>::k];
    if constexpr (GT<J, Q>::fst)
        S[GT<J, Q>::s] = xv[Q] * xrk;
    else
        S[GT<J, Q>::s] = fmaf(xv[Q], xrk, S[GT<J, Q>::s]);
}

template <int J, int S8>
__device__ __forceinline__ void gp_comb(float& acc, const float* S, const float* w) {
    if constexpr (S8 < RN<J>::ns) acc = fmaf(w[SP<J, S8>::p], S[S8], acc);
}

template <int J, std::size_t... Qs>
__device__ __forceinline__ float gp_row(const float* xv, const float* xr, const float* w,
                                        std::index_sequence<Qs...>) {
    float S[8];
    (gp_term<J, (int)Qs>(S, xv, xr), ...);
    float acc = 0.f;
    gp_comb<J, 0>(acc, S, w); gp_comb<J, 1>(acc, S, w);
    gp_comb<J, 2>(acc, S, w); gp_comb<J, 3>(acc, S, w);
    gp_comb<J, 4>(acc, S, w); gp_comb<J, 5>(acc, S, w);
    gp_comb<J, 6>(acc, S, w); gp_comb<J, 7>(acc, S, w);
    return acc;
}

template <int G>
__device__ __forceinline__ void gp_group(float* __restrict__ orow, const float* xv,
                                         const float* xr, const float* w) {
    float4 v;
    v.x = gp_row<4 * G + 0>(xv, xr, w, std::make_index_sequence<64>{});
    v.y = gp_row<4 * G + 1>(xv, xr, w, std::make_index_sequence<64>{});
    v.z = gp_row<4 * G + 2>(xv, xr, w, std::make_index_sequence<64>{});
    v.w = gp_row<4 * G + 3>(xv, xr, w, std::make_index_sequence<64>{});
    *reinterpret_cast<float4*>(orow + 4 * G) = v;
}

template <std::size_t... Gs>
__device__ __forceinline__ void gp_all(float* __restrict__ orow, const float* xv, const float* xr,
                                       const float* w, std::index_sequence<Gs...>) {
    (gp_group<(int)Gs>(orow, xv, xr, w), ...);
}

// ---------------------------------------------------------------------------
// Transposed w_lin scratch: [m][n] float4, tiled transpose (both sides coalesced).
// ---------------------------------------------------------------------------

__device__ float4 g_wlt[NF * NF];

__global__ void wlt_kernel(const float4* __restrict__ w) {
    __shared__ float4 t[16][17];
    const int mb = blockIdx.x & 7;
    const int nb = blockIdx.x >> 3;
    const int tm = threadIdx.x & 15;
    const int tn = threadIdx.x >> 4;

    t[tn][tm] = w[(nb * 16 + tn) * NF + (mb * 16 + tm)];
    __syncthreads();
    g_wlt[(mb * 16 + tn) * NF + (nb * 16 + tm)] = t[tm][tn];
}

// ---------------------------------------------------------------------------
// Fused kernel: one CTA per batch element b, one thread per feature n.
// ---------------------------------------------------------------------------

__global__ void __launch_bounds__(128, 2)
qgp_kernel(const float* __restrict__ x, const float* __restrict__ w_gp,
           const float* __restrict__ b_lin, const float* __restrict__ a_norm,
           float* __restrict__ out) {
    __shared__ __align__(16) float x_s[NF * XS];   // x tile (internal i-order); reused for output

    const int b = blockIdx.x;
    const int n = threadIdx.x;

    // Hoisted small loads — latency hidden under staging/m-loop.
    const float bl   = b_lin[n];
    const float4 an4 = *reinterpret_cast<const float4*>(a_norm + n * 4);

    // Per-thread scatter targets: thread n always handles canonical group c = n&15.
    const int c4 = (n & 15) * 4;
    const int p0 = c_iperm[c4 + 0];
    const int p1 = c_iperm[c4 + 1];
    const int p2 = c_iperm[c4 + 2];
    const int p3 = c_iperm[c4 + 3];

    // Stage x[b] into smem: coalesced gmem float4 reads, permuted scalar smem writes.
    {
        const float4* xg = reinterpret_cast<const float4*>(x + (size_t)b * NF * DV);
#pragma unroll
        for (int t = 0; t < 16; ++t) {
            int idx = t * 128 + n;
            int m = idx >> 4;              // c = idx & 15 == n & 15 (128 % 16 == 0)
            float4 v = xg[idx];
            float* row = x_s + m * XS;
            row[p0] = v.x;
            row[p1] = v.y;
            row[p2] = v.z;
            row[p3] = v.w;
        }
    }
    __syncthreads();

    // ---- Linear phase (packed f32x2, class-blocked): 4 broadcast multipliers/m ----
    u64 acc2[32];
#pragma unroll
    for (int q = 0; q < 32; ++q) acc2[q] = 0ull;

#pragma unroll 4
    for (int m = 0; m < NF; ++m) {
        const float4 w4 = __ldg(&g_wlt[m * NF + n]);   // coalesced, L2-resident
        u64 wq[4];
        asm("mov.b64 %0, {%1,%1};" : "=l"(wq[0]) : "f"(w4.x));
        asm("mov.b64 %0, {%1,%1};" : "=l"(wq[1]) : "f"(w4.y));
        asm("mov.b64 %0, {%1,%1};" : "=l"(wq[2]) : "f"(w4.z));
        asm("mov.b64 %0, {%1,%1};" : "=l"(wq[3]) : "f"(w4.w));
        const ulonglong2* xm = reinterpret_cast<const ulonglong2*>(x_s + m * XS);
        lin_m2(acc2, wq, xm, std::make_index_sequence<16>{});
    }

    float acc[DV];
#pragma unroll
    for (int q = 0; q < 32; ++q)
        asm("mov.b64 {%0,%1}, %2;" : "=f"(acc[2 * q]), "=f"(acc[2 * q + 1]) : "l"(acc2[q]));

    acc[0] += bl;   // canonical index 0 is internal position 0 (static_assert'd)

    // ---- Norms per class, sigmoid gate, scale ----
    float sq[4] = {0.f, 0.f, 0.f, 0.f};
    sq_accum(sq, acc, std::make_index_sequence<64>{});

    float inv[4];
    {
        const float anv[4] = {an4.x, an4.y, an4.z, an4.w};
#pragma unroll
        for (int c = 0; c < 4; ++c) {
            float nrm = sqrtf(sq[c]);
            float sig = 1.f / (1.f + expf(-anv[c]));
            float gate = fmaf(sig, nrm - 1.f, 1.f);
            inv[c] = 1.f / (gate + 1e-6f);
        }
    }

    float xr[DV];
    xr_scale(xr, acc, inv, std::make_index_sequence<64>{});

    // ---- xv = x[b,n,:] (internal order) straight from smem row n ----
    float xv[DV];
#pragma unroll
    for (int t = 0; t < 16; ++t) {
        float4 v = *reinterpret_cast<const float4*>(x_s + n * XS + 4 * t);
        xv[4 * t + 0] = v.x;
        xv[4 * t + 1] = v.y;
        xv[4 * t + 2] = v.z;
        xv[4 * t + 3] = v.w;
    }

    // ---- w_gp row (16 KB total, L2-resident across CTAs) ----
    float w[PN];
    {
        const float4* wg = reinterpret_cast<const float4*>(w_gp + (size_t)n * PN);
#pragma unroll
        for (int t = 0; t < PN / 4; ++t) {
            float4 v = wg[t];
            w[4 * t + 0] = v.x;
            w[4 * t + 1] = v.y;
            w[4 * t + 2] = v.z;
            w[4 * t + 3] = v.w;
        }
    }

    __syncthreads();   // everyone done reading x_s; reuse it for output staging

    // ---- Geometric product into smem row (canonical j order), coalesced copy out ----
    gp_all(x_s + n * XS, xv, xr, w, std::make_index_sequence<16>{});
    __syncthreads();

    {
        float4* og = reinterpret_cast<float4*>(out + (size_t)b * NF * DV);
#pragma unroll
        for (int t = 0; t < 16; ++t) {
            int idx = t * 128 + n;
            int m = idx >> 4, c = idx & 15;
            og[idx] = *reinterpret_cast<const float4*>(x_s + m * XS + c * 4);
        }
    }
}

// ---------------------------------------------------------------------------

extern "C" void kernel_launch(void* const* d_in, const int* in_sizes, int n_in,
                              void* d_out, int out_size) {
    (void)in_sizes; (void)n_in; (void)out_size;
    const float* x      = (const float*)d_in[0];
    const float* w_gp   = (const float*)d_in[1];
    const float* w_lin  = (const float*)d_in[2];
    const float* b_lin  = (const float*)d_in[3];
    const float* a_norm = (const float*)d_in[4];
    float* out = (float*)d_out;

    wlt_kernel<<<64, 256>>>((const float4*)w_lin);
    qgp_kernel<<<NB, NF>>>(x, w_gp, b_lin, a_norm, out);
}